// round 9
// baseline (speedup 1.0000x reference)
#include <cuda_runtime.h>
#include <math.h>

#define BATCH 8
#define SEQ 1024
#define DIM 512
#define HEADS 8
#define HDIM 64
#define VOCAB 1024
#define M_ROWS (BATCH*SEQ)          /* 8192 */
#define MTOT (M_ROWS*DIM)           /* 4,194,304 floats */
#define EPSF 1e-5f

// ---------------- scratch (device globals; no allocation allowed) ----------------
__device__ float g_x[MTOT];   // 0: x (post embed-LN), later LN(x2)
__device__ float g_q[MTOT];   // 1: q proj, later FFN hidden
__device__ float g_k[MTOT];   // 2: k proj, later final LN output
__device__ float g_v[MTOT];   // 3: v proj, later x4
__device__ float g_g[MTOT];   // 4: gate proj, later gated value z
__device__ float g_y[MTOT];   // 5: retention output (group-normed)
__device__ float g_t[MTOT];   // 6: x2 = z@Wo + x (residual carrier)

__device__ __forceinline__ float* buf(int s) {
    switch (s) {
        case 0: return g_x;
        case 1: return g_q;
        case 2: return g_k;
        case 3: return g_v;
        case 4: return g_g;
        case 5: return g_y;
        default: return g_t;
    }
}

// ---------------- embed + layernorm (warp per row) ----------------
__global__ void embed_ln_kernel(const int* __restrict__ ids,
                                const float* __restrict__ tables,
                                const float* __restrict__ pos,
                                const float* __restrict__ gam,
                                const float* __restrict__ bet) {
    int warp = (blockIdx.x * blockDim.x + threadIdx.x) >> 5;
    if (warp >= M_ROWS) return;
    int lane = threadIdx.x & 31;
    int s = warp & (SEQ - 1);
    int id = ids[2 * BATCH * SEQ + warp];
    const float4* t4 = (const float4*)(tables + (size_t)(2 * VOCAB + id) * DIM);
    const float4* p4 = (const float4*)(pos + (size_t)(2 * SEQ + s) * DIM);
    float4 v[4];
    float s1 = 0.f, s2 = 0.f;
#pragma unroll
    for (int k = 0; k < 4; k++) {
        int c4 = lane + k * 32;
        float4 a = t4[c4], b = p4[c4];
        v[k] = make_float4(a.x + b.x, a.y + b.y, a.z + b.z, a.w + b.w);
        s1 += v[k].x + v[k].y + v[k].z + v[k].w;
        s2 += v[k].x * v[k].x + v[k].y * v[k].y + v[k].z * v[k].z + v[k].w * v[k].w;
    }
#pragma unroll
    for (int o = 16; o; o >>= 1) {
        s1 += __shfl_xor_sync(0xffffffffu, s1, o);
        s2 += __shfl_xor_sync(0xffffffffu, s2, o);
    }
    float mean = s1 * (1.f / DIM);
    float var = s2 * (1.f / DIM) - mean * mean;
    float r = rsqrtf(var + EPSF);
    float4* out4 = (float4*)(g_x + (size_t)warp * DIM);
#pragma unroll
    for (int k = 0; k < 4; k++) {
        int c4 = lane + k * 32;
        float4 gm = ((const float4*)gam)[c4];
        float4 bt = ((const float4*)bet)[c4];
        float4 o;
        o.x = (v[k].x - mean) * r * gm.x + bt.x;
        o.y = (v[k].y - mean) * r * gm.y + bt.y;
        o.z = (v[k].z - mean) * r * gm.z + bt.z;
        o.w = (v[k].w - mean) * r * gm.w + bt.w;
        out4[c4] = o;
    }
}

// ---------------- plain layernorm (warp per row), selector-based ----------------
__global__ void ln_kernel(int in_sel, int out_sel,
                          const float* __restrict__ gam,
                          const float* __restrict__ bet) {
    int warp = (blockIdx.x * blockDim.x + threadIdx.x) >> 5;
    if (warp >= M_ROWS) return;
    int lane = threadIdx.x & 31;
    const float* in = buf(in_sel);
    float* out = buf(out_sel);
    const float4* src = (const float4*)(in + (size_t)warp * DIM);
    float4 v[4];
    float s1 = 0.f, s2 = 0.f;
#pragma unroll
    for (int k = 0; k < 4; k++) {
        int c4 = lane + k * 32;
        v[k] = src[c4];
        s1 += v[k].x + v[k].y + v[k].z + v[k].w;
        s2 += v[k].x * v[k].x + v[k].y * v[k].y + v[k].z * v[k].z + v[k].w * v[k].w;
    }
#pragma unroll
    for (int o = 16; o; o >>= 1) {
        s1 += __shfl_xor_sync(0xffffffffu, s1, o);
        s2 += __shfl_xor_sync(0xffffffffu, s2, o);
    }
    float mean = s1 * (1.f / DIM);
    float var = s2 * (1.f / DIM) - mean * mean;
    float r = rsqrtf(var + EPSF);
    float4* out4 = (float4*)(out + (size_t)warp * DIM);
#pragma unroll
    for (int k = 0; k < 4; k++) {
        int c4 = lane + k * 32;
        float4 gm = ((const float4*)gam)[c4];
        float4 bt = ((const float4*)bet)[c4];
        float4 o;
        o.x = (v[k].x - mean) * r * gm.x + bt.x;
        o.y = (v[k].y - mean) * r * gm.y + bt.y;
        o.z = (v[k].z - mean) * r * gm.z + bt.z;
        o.w = (v[k].w - mean) * r * gm.w + bt.w;
        out4[c4] = o;
    }
}

// ---------------- SGEMM: C[M,512] = A[M,512] @ W[512,512] (+bias)(+relu)(+res) ----------------
// Double-buffered smem (1 sync per k-tile) + register-prefetched global loads.
// Multi-weight: grid.x = 4*num_weights; which = blockIdx.x>>2 selects B0..B3 and
// the 4-bit output selector packed in cpack. Generic calls use grid.x=4 (which=0).
// flags: bit0 bias, bit1 relu, bit2 residual-add.
#define GBM 128
#define GBN 128
#define GBK 8
#define KTILES (DIM / GBK)
__global__ __launch_bounds__(256) void sgemm_kernel(int a_sel,
                                                    const float* __restrict__ B0,
                                                    const float* __restrict__ B1,
                                                    const float* __restrict__ B2,
                                                    const float* __restrict__ B3,
                                                    int cpack,
                                                    const float* __restrict__ bias,
                                                    int res_sel,
                                                    int flags) {
    __shared__ float As[2][GBK][GBM];
    __shared__ float Bs[2][GBK][GBN];
    int which = blockIdx.x >> 2;
    const float* B = (which == 0) ? B0 : (which == 1) ? B1 : (which == 2) ? B2 : B3;
    const float* A = buf(a_sel);
    float* C = buf((cpack >> (8 * which)) & 0xf);
    int tid = threadIdx.x;
    int bm = blockIdx.y * GBM;
    int bn = (blockIdx.x & 3) * GBN;
    int tx = tid & 15, ty = tid >> 4;
    float acc[8][8] = {};
    int arow = tid >> 1, acol = (tid & 1) * 4;
    int brow = tid >> 5, bcol = (tid & 31) * 4;
    const float* Aptr = A + (size_t)(bm + arow) * DIM + acol;
    const float* Bptr = B + (size_t)brow * DIM + bn + bcol;

    // stage 0
    float4 a = *(const float4*)(Aptr);
    float4 b = *(const float4*)(Bptr);
    As[0][acol + 0][arow] = a.x;
    As[0][acol + 1][arow] = a.y;
    As[0][acol + 2][arow] = a.z;
    As[0][acol + 3][arow] = a.w;
    *(float4*)&Bs[0][brow][bcol] = b;
    __syncthreads();

    for (int t = 0; t < KTILES; t++) {
        int cur = t & 1;
        if (t + 1 < KTILES) {   // prefetch next tile into registers
            a = *(const float4*)(Aptr + (t + 1) * GBK);
            b = *(const float4*)(Bptr + (size_t)((t + 1) * GBK) * DIM);
        }
#pragma unroll
        for (int k = 0; k < GBK; k++) {
            float ar[8], br[8];
            *(float4*)(&ar[0]) = *(const float4*)(&As[cur][k][ty * 8]);
            *(float4*)(&ar[4]) = *(const float4*)(&As[cur][k][ty * 8 + 4]);
            *(float4*)(&br[0]) = *(const float4*)(&Bs[cur][k][tx * 8]);
            *(float4*)(&br[4]) = *(const float4*)(&Bs[cur][k][tx * 8 + 4]);
#pragma unroll
            for (int i = 0; i < 8; i++)
#pragma unroll
                for (int j = 0; j < 8; j++) acc[i][j] += ar[i] * br[j];
        }
        if (t + 1 < KTILES) {   // store into the other stage; one sync per tile
            int nxt = cur ^ 1;
            As[nxt][acol + 0][arow] = a.x;
            As[nxt][acol + 1][arow] = a.y;
            As[nxt][acol + 2][arow] = a.z;
            As[nxt][acol + 3][arow] = a.w;
            *(float4*)&Bs[nxt][brow][bcol] = b;
            __syncthreads();
        }
    }

    bool hb = flags & 1, hr = flags & 2, hres = flags & 4;
    const float* res = hres ? buf(res_sel) : (const float*)0;
    float bvals[8];
#pragma unroll
    for (int j = 0; j < 8; j++) bvals[j] = hb ? bias[bn + tx * 8 + j] : 0.f;
#pragma unroll
    for (int i = 0; i < 8; i++) {
        int row = bm + ty * 8 + i;
        float* crow = C + (size_t)row * DIM + bn + tx * 8;
#pragma unroll
        for (int j = 0; j < 8; j++) {
            float v = acc[i][j] + bvals[j];
            if (hr) v = fmaxf(v, 0.f);
            crow[j] = v;
        }
        if (hres) {
            const float* rrow = res + (size_t)row * DIM + bn + tx * 8;
#pragma unroll
            for (int j = 0; j < 8; j++) crow[j] += rrow[j];
        }
    }
}

// ---------------- fused causal retention + per-head group norm ----------------
// grid (SEQ/64, HEADS, BATCH), 256 threads, STATIC smem (42.5 KB, no opt-in).
#define QS 68
#define KS 34
#define SS 36
__global__ __launch_bounds__(256) void retention_kernel() {
    __shared__ float QsT[64 * QS];   // [d][n] : QsT[d*68 + n]
    __shared__ float KsT[64 * KS];   // [d][m] : KsT[d*34 + m], m in 0..31
    __shared__ float Vs[32 * 64];    // [m][c] : Vs[m*64 + c]
    __shared__ float Ss[64 * SS];    // [n][m] : Ss[n*36 + m]
    int b = blockIdx.z, h = blockIdx.y;
    int n0 = blockIdx.x * 64;
    int tid = threadIdx.x;
    int tx = tid & 15, ty = tid >> 4;
    float gamma = 1.f - exp2f(-5.f - (float)h);
    float l2g = log2f(gamma);

    {   // load Q tile (64 rows x 64 d), transposed into QsT
        int row = tid >> 2, cq = tid & 3;
        const float* src = g_q + ((size_t)(b * SEQ + n0 + row)) * DIM + h * HDIM;
#pragma unroll
        for (int rep = 0; rep < 4; rep++) {
            int c = (cq + rep * 4) * 4;
            float4 v = *(const float4*)(src + c);
            QsT[(c + 0) * QS + row] = v.x;
            QsT[(c + 1) * QS + row] = v.y;
            QsT[(c + 2) * QS + row] = v.z;
            QsT[(c + 3) * QS + row] = v.w;
        }
    }

    float acc[4][4] = {};
    for (int m0 = 0; m0 <= n0 + 32; m0 += 32) {
        __syncthreads();
        {   // load K (transposed) + V (natural), 32 rows x 64 cols each
            int row = tid >> 3, cq = tid & 7;
            const float* ksrc = g_k + ((size_t)(b * SEQ + m0 + row)) * DIM + h * HDIM;
            const float* vsrc = g_v + ((size_t)(b * SEQ + m0 + row)) * DIM + h * HDIM;
#pragma unroll
            for (int rep = 0; rep < 2; rep++) {
                int c = cq * 8 + rep * 4;
                float4 kv = *(const float4*)(ksrc + c);
                KsT[(c + 0) * KS + row] = kv.x;
                KsT[(c + 1) * KS + row] = kv.y;
                KsT[(c + 2) * KS + row] = kv.z;
                KsT[(c + 3) * KS + row] = kv.w;
                *(float4*)&Vs[row * 64 + c] = *(const float4*)(vsrc + c);
            }
        }
        __syncthreads();
        // stage 1: s[4n][2m] = q . k
        float s[4][2] = {};
#pragma unroll 8
        for (int d = 0; d < 64; d++) {
            float a[4], bb[2];
            *(float4*)a  = *(const float4*)&QsT[d * QS + ty * 4];
            *(float2*)bb = *(const float2*)&KsT[d * KS + tx * 2];
#pragma unroll
            for (int i = 0; i < 4; i++)
#pragma unroll
                for (int j = 0; j < 2; j++) s[i][j] += a[i] * bb[j];
        }
#pragma unroll
        for (int i = 0; i < 4; i++)
#pragma unroll
            for (int j = 0; j < 2; j++) {
                int diff = (n0 + ty * 4 + i) - (m0 + tx * 2 + j);
                float val = (diff < 0) ? 0.f
                          : s[i][j] * 0.125f * exp2f((float)diff * l2g);
                Ss[(ty * 4 + i) * SS + tx * 2 + j] = val;
            }
        __syncthreads();
        // stage 2: acc[4n][4c] += S V
#pragma unroll 8
        for (int m = 0; m < 32; m++) {
            float a[4], bb[4];
#pragma unroll
            for (int i = 0; i < 4; i++) a[i] = Ss[(ty * 4 + i) * SS + m];
            *(float4*)bb = *(const float4*)&Vs[m * 64 + tx * 4];
#pragma unroll
            for (int i = 0; i < 4; i++)
#pragma unroll
                for (int j = 0; j < 4; j++) acc[i][j] += a[i] * bb[j];
        }
    }

    // per-row group norm over hd=64
#pragma unroll
    for (int i = 0; i < 4; i++) {
        float s1 = acc[i][0] + acc[i][1] + acc[i][2] + acc[i][3];
        float s2 = acc[i][0] * acc[i][0] + acc[i][1] * acc[i][1] +
                   acc[i][2] * acc[i][2] + acc[i][3] * acc[i][3];
#pragma unroll
        for (int o = 8; o; o >>= 1) {
            s1 += __shfl_xor_sync(0xffffffffu, s1, o);
            s2 += __shfl_xor_sync(0xffffffffu, s2, o);
        }
        float mean = s1 * (1.f / 64.f);
        float var = s2 * (1.f / 64.f) - mean * mean;
        float r = rsqrtf(var + EPSF);
        int n = n0 + ty * 4 + i;
        float4 o4;
        o4.x = (acc[i][0] - mean) * r;
        o4.y = (acc[i][1] - mean) * r;
        o4.z = (acc[i][2] - mean) * r;
        o4.w = (acc[i][3] - mean) * r;
        *(float4*)&g_y[((size_t)(b * SEQ + n)) * DIM + h * HDIM + tx * 4] = o4;
    }
}

// ---------------- gate: z = swish(xg) * y (in place into g_g) ----------------
__global__ void gate_kernel() {
    int i = blockIdx.x * blockDim.x + threadIdx.x;
    float4 g = ((const float4*)g_g)[i];
    float4 y = ((const float4*)g_y)[i];
    float4 o;
    o.x = g.x * y.x / (1.f + expf(-g.x));
    o.y = g.y * y.y / (1.f + expf(-g.y));
    o.z = g.z * y.z / (1.f + expf(-g.z));
    o.w = g.w * y.w / (1.f + expf(-g.w));
    ((float4*)g_g)[i] = o;
}

// ---------------- final: out[b] = sigmoid(x5[b].flatten() . fc_W + fc_b) ----------------
__global__ void final_kernel(int in_sel,
                             const float* __restrict__ w,
                             const float* __restrict__ bias,
                             float* __restrict__ out) {
    int b = blockIdx.x;
    const float* x = buf(in_sel);
    const float4* xr = (const float4*)(x + (size_t)b * SEQ * DIM);
    const float4* wr = (const float4*)w;
    float sum = 0.f;
    const int n4 = SEQ * DIM / 4;
    for (int i = threadIdx.x; i < n4; i += blockDim.x) {
        float4 a = xr[i], c = wr[i];
        sum += a.x * c.x + a.y * c.y + a.z * c.z + a.w * c.w;
    }
    __shared__ float red[32];
#pragma unroll
    for (int o = 16; o; o >>= 1) sum += __shfl_xor_sync(0xffffffffu, sum, o);
    if ((threadIdx.x & 31) == 0) red[threadIdx.x >> 5] = sum;
    __syncthreads();
    if (threadIdx.x < 32) {
        float v = (threadIdx.x < (int)(blockDim.x >> 5)) ? red[threadIdx.x] : 0.f;
#pragma unroll
        for (int o = 16; o; o >>= 1) v += __shfl_xor_sync(0xffffffffu, v, o);
        if (threadIdx.x == 0) out[b] = 1.f / (1.f + expf(-(v + bias[0])));
    }
}

// ---------------- launch: kernel launches ONLY ----------------
extern "C" void kernel_launch(void* const* d_in, const int* in_sizes, int n_in,
                              void* d_out, int out_size) {
    (void)in_sizes; (void)n_in; (void)out_size;
    const int*   ids    = (const int*)d_in[0];
    const float* tables = (const float*)d_in[1];
    const float* pos    = (const float*)d_in[2];
    const float* lng    = (const float*)d_in[3];
    const float* lnb    = (const float*)d_in[4];
    const float* Wq     = (const float*)d_in[5];
    const float* Wk     = (const float*)d_in[6];
    const float* Wv     = (const float*)d_in[7];
    const float* Wg     = (const float*)d_in[8];
    const float* Wo     = (const float*)d_in[9];
    const float* W1     = (const float*)d_in[10];
    const float* b1     = (const float*)d_in[11];
    const float* W2     = (const float*)d_in[12];
    const float* b2     = (const float*)d_in[13];
    const float* fcW    = (const float*)d_in[14];
    const float* fcb    = (const float*)d_in[15];
    float* out = (float*)d_out;

    dim3 g1(4, M_ROWS / GBM);    // single-weight GEMM: 256 blocks
    dim3 g4(16, M_ROWS / GBM);   // fused QKVG GEMM: 1024 blocks

    // Only the last vocab pass (i = NVOCAB-1 = 2) survives in the reference.
    embed_ln_kernel<<<M_ROWS / 8, 256>>>(ids, tables, pos, lng, lnb);        // -> g_x(0)
    // q(1), k(2), v(3), gate(4) in ONE launch: cpack = 0x04030201
    sgemm_kernel<<<g4, 256>>>(0, Wq, Wk, Wv, Wg, 0x04030201, nullptr, 0, 0);
    retention_kernel<<<dim3(SEQ / 64, HEADS, BATCH), 256>>>();               // -> g_y(5)
    gate_kernel<<<MTOT / 4 / 256, 256>>>();                                  // g_g = z
    sgemm_kernel<<<g1, 256>>>(4, Wo, Wo, Wo, Wo, 6, nullptr, 0, 4);          // x2 = z@Wo + x(0)... res_sel=0
    ln_kernel<<<M_ROWS / 8, 256>>>(6, 0, lng, lnb);                          // x3 = LN(x2)
    sgemm_kernel<<<g1, 256>>>(0, W1, W1, W1, W1, 1, b1, 0, 3);               // h = relu(x3@W1+b1)
    sgemm_kernel<<<g1, 256>>>(1, W2, W2, W2, W2, 3, b2, 6, 5);               // x4 = h@W2+b2+x2
    ln_kernel<<<M_ROWS / 8, 256>>>(3, 2, lng, lnb);                          // x5 = LN(x4)
    final_kernel<<<BATCH, 1024>>>(2, fcW, fcb, out);
}

// round 12
// speedup vs baseline: 1.4001x; 1.4001x over previous
#include <cuda_runtime.h>
#include <cuda_bf16.h>
#include <math.h>
#include <stdint.h>

#define BATCH 8
#define SEQ 1024
#define DIM 512
#define HEADS 8
#define HDIM 64
#define VOCAB 1024
#define M_ROWS (BATCH*SEQ)          /* 8192 */
#define MTOT (M_ROWS*DIM)           /* 4,194,304 floats */
#define EPSF 1e-5f

// ---------------- scratch (device globals; no allocation allowed) ----------------
__device__ float g_x[MTOT];   // 0: x (post embed-LN)
__device__ float g_q[MTOT];   // 1: q proj
__device__ float g_k[MTOT];   // 2: k proj / final LN output
__device__ float g_v[MTOT];   // 3: v proj / x4
__device__ float g_g[MTOT];   // 4: gate proj / z
__device__ float g_y[MTOT];   // 5: retention output (group-normed)
__device__ float g_t[MTOT];   // 6: x2 = z@Wo + x (residual carrier)

// bf16 split activation buffers (A operands for MMA GEMMs)
__device__ __nv_bfloat16 g_ah[MTOT];   // a-pair hi
__device__ __nv_bfloat16 g_al[MTOT];   // a-pair lo
__device__ __nv_bfloat16 g_bh[MTOT];   // b-pair hi (FFN hidden)
__device__ __nv_bfloat16 g_bl[MTOT];   // b-pair lo

// bf16 split transposed weights: 7 matrices [n][k], idx: Wq,Wk,Wv,Wg,Wo,W1,W2
__device__ __nv_bfloat16 g_wh[7 * DIM * DIM];
__device__ __nv_bfloat16 g_wl[7 * DIM * DIM];

__device__ __forceinline__ float* buf(int s) {
    switch (s) {
        case 0: return g_x;
        case 1: return g_q;
        case 2: return g_k;
        case 3: return g_v;
        case 4: return g_g;
        case 5: return g_y;
        default: return g_t;
    }
}

__device__ __forceinline__ void split_store(__nv_bfloat16* hp, __nv_bfloat16* lp,
                                            size_t idx, float v) {
    __nv_bfloat16 h = __float2bfloat16(v);
    hp[idx] = h;
    lp[idx] = __float2bfloat16(v - __bfloat162float(h));
}

__device__ __forceinline__ uint32_t smem_u32(const void* p) {
    uint32_t a;
    asm("{ .reg .u64 t; cvta.to.shared.u64 t, %1; cvt.u32.u64 %0, t; }"
        : "=r"(a) : "l"(p));
    return a;
}

// ---------------- mma.sync helpers (baseline ISA, compiles for compute_103) ----------------
__device__ __forceinline__ void ldsm4(uint32_t* r, uint32_t addr) {
    asm volatile("ldmatrix.sync.aligned.m8n8.x4.shared.b16 {%0,%1,%2,%3}, [%4];"
                 : "=r"(r[0]), "=r"(r[1]), "=r"(r[2]), "=r"(r[3]) : "r"(addr));
}
__device__ __forceinline__ void mma_bf16(float* d, const uint32_t* a, const uint32_t* b) {
    asm volatile("mma.sync.aligned.m16n8k16.row.col.f32.bf16.bf16.f32 "
                 "{%0,%1,%2,%3}, {%4,%5,%6,%7}, {%8,%9}, {%0,%1,%2,%3};"
                 : "+f"(d[0]), "+f"(d[1]), "+f"(d[2]), "+f"(d[3])
                 : "r"(a[0]), "r"(a[1]), "r"(a[2]), "r"(a[3]), "r"(b[0]), "r"(b[1]));
}

// ---------------- weight convert: transpose + bf16 hi/lo split ----------------
// grid (16, 16, 7), block (32, 8)
__global__ void convert_weights_kernel(const float* __restrict__ Wq, const float* __restrict__ Wk,
                                       const float* __restrict__ Wv, const float* __restrict__ Wg,
                                       const float* __restrict__ Wo, const float* __restrict__ W1,
                                       const float* __restrict__ W2) {
    __shared__ float tile[32][33];
    int widx = blockIdx.z;
    const float* W = (widx == 0) ? Wq : (widx == 1) ? Wk : (widx == 2) ? Wv
                   : (widx == 3) ? Wg : (widx == 4) ? Wo : (widx == 5) ? W1 : W2;
    int k0 = blockIdx.x * 32, n0 = blockIdx.y * 32;
    int tx = threadIdx.x, ty = threadIdx.y;
#pragma unroll
    for (int r = 0; r < 32; r += 8)
        tile[ty + r][tx] = W[(size_t)(k0 + ty + r) * DIM + n0 + tx];
    __syncthreads();
    size_t base = (size_t)widx * DIM * DIM;
#pragma unroll
    for (int r = 0; r < 32; r += 8) {
        float v = tile[tx][ty + r];   // = W[k0+tx][n0+ty+r]
        size_t o = base + (size_t)(n0 + ty + r) * DIM + k0 + tx;
        __nv_bfloat16 h = __float2bfloat16(v);
        g_wh[o] = h;
        g_wl[o] = __float2bfloat16(v - __bfloat162float(h));
    }
}

// ---------------- embed + layernorm (warp per row) + bf16 split out ----------------
__global__ void embed_ln_kernel(const int* __restrict__ ids,
                                const float* __restrict__ tables,
                                const float* __restrict__ pos,
                                const float* __restrict__ gam,
                                const float* __restrict__ bet) {
    int warp = (blockIdx.x * blockDim.x + threadIdx.x) >> 5;
    if (warp >= M_ROWS) return;
    int lane = threadIdx.x & 31;
    int s = warp & (SEQ - 1);
    int id = ids[2 * BATCH * SEQ + warp];
    const float4* t4 = (const float4*)(tables + (size_t)(2 * VOCAB + id) * DIM);
    const float4* p4 = (const float4*)(pos + (size_t)(2 * SEQ + s) * DIM);
    float4 v[4];
    float s1 = 0.f, s2 = 0.f;
#pragma unroll
    for (int k = 0; k < 4; k++) {
        int c4 = lane + k * 32;
        float4 a = t4[c4], b = p4[c4];
        v[k] = make_float4(a.x + b.x, a.y + b.y, a.z + b.z, a.w + b.w);
        s1 += v[k].x + v[k].y + v[k].z + v[k].w;
        s2 += v[k].x * v[k].x + v[k].y * v[k].y + v[k].z * v[k].z + v[k].w * v[k].w;
    }
#pragma unroll
    for (int o = 16; o; o >>= 1) {
        s1 += __shfl_xor_sync(0xffffffffu, s1, o);
        s2 += __shfl_xor_sync(0xffffffffu, s2, o);
    }
    float mean = s1 * (1.f / DIM);
    float var = s2 * (1.f / DIM) - mean * mean;
    float r = rsqrtf(var + EPSF);
    size_t rowoff = (size_t)warp * DIM;
    float4* out4 = (float4*)(g_x + rowoff);
#pragma unroll
    for (int k = 0; k < 4; k++) {
        int c4 = lane + k * 32;
        float4 gm = ((const float4*)gam)[c4];
        float4 bt = ((const float4*)bet)[c4];
        float4 o;
        o.x = (v[k].x - mean) * r * gm.x + bt.x;
        o.y = (v[k].y - mean) * r * gm.y + bt.y;
        o.z = (v[k].z - mean) * r * gm.z + bt.z;
        o.w = (v[k].w - mean) * r * gm.w + bt.w;
        out4[c4] = o;
        size_t i0 = rowoff + c4 * 4;
        split_store(g_ah, g_al, i0 + 0, o.x);
        split_store(g_ah, g_al, i0 + 1, o.y);
        split_store(g_ah, g_al, i0 + 2, o.z);
        split_store(g_ah, g_al, i0 + 3, o.w);
    }
}

// ---------------- plain layernorm (warp per row) + bf16 split out ----------------
__global__ void ln_kernel(int in_sel, int out_sel,
                          const float* __restrict__ gam,
                          const float* __restrict__ bet) {
    int warp = (blockIdx.x * blockDim.x + threadIdx.x) >> 5;
    if (warp >= M_ROWS) return;
    int lane = threadIdx.x & 31;
    const float* in = buf(in_sel);
    float* out = buf(out_sel);
    const float4* src = (const float4*)(in + (size_t)warp * DIM);
    float4 v[4];
    float s1 = 0.f, s2 = 0.f;
#pragma unroll
    for (int k = 0; k < 4; k++) {
        int c4 = lane + k * 32;
        v[k] = src[c4];
        s1 += v[k].x + v[k].y + v[k].z + v[k].w;
        s2 += v[k].x * v[k].x + v[k].y * v[k].y + v[k].z * v[k].z + v[k].w * v[k].w;
    }
#pragma unroll
    for (int o = 16; o; o >>= 1) {
        s1 += __shfl_xor_sync(0xffffffffu, s1, o);
        s2 += __shfl_xor_sync(0xffffffffu, s2, o);
    }
    float mean = s1 * (1.f / DIM);
    float var = s2 * (1.f / DIM) - mean * mean;
    float r = rsqrtf(var + EPSF);
    size_t rowoff = (size_t)warp * DIM;
    float4* out4 = (float4*)(out + rowoff);
#pragma unroll
    for (int k = 0; k < 4; k++) {
        int c4 = lane + k * 32;
        float4 gm = ((const float4*)gam)[c4];
        float4 bt = ((const float4*)bet)[c4];
        float4 o;
        o.x = (v[k].x - mean) * r * gm.x + bt.x;
        o.y = (v[k].y - mean) * r * gm.y + bt.y;
        o.z = (v[k].z - mean) * r * gm.z + bt.z;
        o.w = (v[k].w - mean) * r * gm.w + bt.w;
        out4[c4] = o;
        size_t i0 = rowoff + c4 * 4;
        split_store(g_ah, g_al, i0 + 0, o.x);
        split_store(g_ah, g_al, i0 + 1, o.y);
        split_store(g_ah, g_al, i0 + 2, o.z);
        split_store(g_ah, g_al, i0 + 3, o.w);
    }
}

// ---------------- HMMA split-bf16 GEMM ----------------
// C[M_ROWS,512] = A @ W. A = Ahi+Alo (bf16 pairs). W in g_wh/g_wl transposed [n][k]
// (= col-major B for mma .row.col). D = Ah*Wh + Ah*Wl + Al*Wh, fp32 accum.
// CTA tile 128x128, K-chunk 32, 8 warps (4m x 2n), warp tile 32x64 (2 m-frags x 8 n-frags).
// Phase 0 (steps 0-15): Ah*(Wh+Wl). Phase 1 (16-31): Al*Wh.
// flags: 1 bias, 2 relu, 4 residual, 8 write bf16 b-pair
#define SROW 40   /* smem row stride in bf16 elements (80 B: 16B-aligned, ldmatrix conflict-free) */
__global__ __launch_bounds__(256, 2) void mma_gemm_kernel(int a_sel, int wbase, int cpack,
                                                          const float* __restrict__ bias,
                                                          int res_sel, int flags) {
    __shared__ __nv_bfloat16 sA[128 * SROW];
    __shared__ __nv_bfloat16 sBh[128 * SROW];
    __shared__ __nv_bfloat16 sBl[128 * SROW];
    const int tid = threadIdx.x;
    const int lane = tid & 31, wid = tid >> 5;
    const int wm = wid & 3, wn = wid >> 2;      // warp covers rows wm*32.., cols wn*64..
    const int which = blockIdx.x >> 2;
    const int bn = (blockIdx.x & 3) * 128;
    const int bm = blockIdx.y * 128;
    const size_t woff = (size_t)(wbase + which) * DIM * DIM;
    const __nv_bfloat16* Ah = a_sel ? g_bh : g_ah;
    const __nv_bfloat16* Al = a_sel ? g_bl : g_al;

    // cooperative loaders: 2 threads per row, 16 bf16 (2x uint4) each
    const int lrow = tid >> 1, lhalf = tid & 1;
    const int sOff = lrow * SROW + lhalf * 16;                 // smem element offset
    const size_t aRow = (size_t)(bm + lrow) * DIM + lhalf * 16;
    const size_t bRow = woff + (size_t)(bn + lrow) * DIM + lhalf * 16;

    // ldmatrix per-lane static byte offsets
    const int mtx = lane >> 3, lr = lane & 7;
    const uint32_t aBase = smem_u32(sA), bhBase = smem_u32(sBh), blBase = smem_u32(sBl);
    // A matrices: m = (mtx&1)*8 + lr, k = (mtx>>1)*8
    const uint32_t aOff = (uint32_t)(((mtx & 1) * 8 + lr) * (SROW * 2) + (mtx >> 1) * 16);
    // B matrices: n = (mtx>>1)*8 + lr, k = (mtx&1)*8
    const uint32_t bOff = (uint32_t)(((mtx >> 1) * 8 + lr) * (SROW * 2) + (mtx & 1) * 16);

    float acc[2][8][4];
#pragma unroll
    for (int i = 0; i < 2; i++)
#pragma unroll
        for (int j = 0; j < 8; j++)
#pragma unroll
            for (int c = 0; c < 4; c++) acc[i][j][c] = 0.f;

    uint4 pa0, pa1, pbh0, pbh1, pbl0, pbl1;
#define FETCH(step) do {                                                    \
        int ph_ = (step) >> 4, k0_ = ((step) & 15) * 32;                    \
        const __nv_bfloat16* As_ = ph_ ? Al : Ah;                           \
        pa0  = *(const uint4*)(As_ + aRow + k0_);                           \
        pa1  = *(const uint4*)(As_ + aRow + k0_ + 8);                       \
        pbh0 = *(const uint4*)(g_wh + bRow + k0_);                          \
        pbh1 = *(const uint4*)(g_wh + bRow + k0_ + 8);                      \
        if (ph_ == 0) {                                                     \
            pbl0 = *(const uint4*)(g_wl + bRow + k0_);                      \
            pbl1 = *(const uint4*)(g_wl + bRow + k0_ + 8);                  \
        }                                                                   \
    } while (0)
#define STORE(step) do {                                                    \
        int ph_ = (step) >> 4;                                              \
        *(uint4*)(sA + sOff) = pa0;  *(uint4*)(sA + sOff + 8) = pa1;        \
        *(uint4*)(sBh + sOff) = pbh0; *(uint4*)(sBh + sOff + 8) = pbh1;     \
        if (ph_ == 0) { *(uint4*)(sBl + sOff) = pbl0;                       \
                        *(uint4*)(sBl + sOff + 8) = pbl1; }                 \
    } while (0)

    FETCH(0);
    STORE(0);
    __syncthreads();
#pragma unroll 1
    for (int step = 0; step < 32; step++) {
        int ph = step >> 4;
        if (step < 31) FETCH(step + 1);
#pragma unroll
        for (int ks = 0; ks < 2; ks++) {
            uint32_t a[2][4];
            ldsm4(a[0], aBase + (uint32_t)((wm * 32) * (SROW * 2)) + ks * 32 + aOff);
            ldsm4(a[1], aBase + (uint32_t)((wm * 32 + 16) * (SROW * 2)) + ks * 32 + aOff);
#pragma unroll
            for (int nfp = 0; nfp < 4; nfp++) {
                uint32_t b[4];
                uint32_t bo = (uint32_t)((wn * 64 + nfp * 16) * (SROW * 2)) + ks * 32 + bOff;
                ldsm4(b, bhBase + bo);
                mma_bf16(acc[0][2 * nfp],     a[0], b + 0);
                mma_bf16(acc[0][2 * nfp + 1], a[0], b + 2);
                mma_bf16(acc[1][2 * nfp],     a[1], b + 0);
                mma_bf16(acc[1][2 * nfp + 1], a[1], b + 2);
                if (ph == 0) {
                    ldsm4(b, blBase + bo);
                    mma_bf16(acc[0][2 * nfp],     a[0], b + 0);
                    mma_bf16(acc[0][2 * nfp + 1], a[0], b + 2);
                    mma_bf16(acc[1][2 * nfp],     a[1], b + 0);
                    mma_bf16(acc[1][2 * nfp + 1], a[1], b + 2);
                }
            }
        }
        if (step < 31) {
            __syncthreads();
            STORE(step + 1);
            __syncthreads();
        }
    }
#undef FETCH
#undef STORE

    // epilogue: thread lane l holds rows group,+8; cols tig*2,+1 of each frag
    bool hb = flags & 1, hr = flags & 2, hres = flags & 4, hbf = flags & 8;
    float* C = buf((cpack >> (8 * which)) & 0xf);
    const float* res = hres ? buf(res_sel) : (const float*)0;
    int group = lane >> 2, tig = lane & 3;
#pragma unroll
    for (int mf = 0; mf < 2; mf++) {
#pragma unroll
        for (int nf = 0; nf < 8; nf++) {
            int row0 = bm + wm * 32 + mf * 16 + group;
            int col = bn + wn * 64 + nf * 8 + tig * 2;
            float b0 = hb ? bias[col] : 0.f;
            float b1 = hb ? bias[col + 1] : 0.f;
#pragma unroll
            for (int half = 0; half < 2; half++) {
                int row = row0 + half * 8;
                float v0 = acc[mf][nf][half * 2 + 0] + b0;
                float v1 = acc[mf][nf][half * 2 + 1] + b1;
                if (hr) { v0 = fmaxf(v0, 0.f); v1 = fmaxf(v1, 0.f); }
                size_t co = (size_t)row * DIM + col;
                if (hres) {
                    float2 rr = *(const float2*)(res + co);
                    v0 += rr.x; v1 += rr.y;
                }
                *(float2*)(C + co) = make_float2(v0, v1);
                if (hbf) {
                    split_store(g_bh, g_bl, co, v0);
                    split_store(g_bh, g_bl, co + 1, v1);
                }
            }
        }
    }
}

// ---------------- fused causal retention + per-head group norm (fp32) ----------------
#define QS 68
#define KS 34
#define SS 36
__global__ __launch_bounds__(256) void retention_kernel() {
    __shared__ float QsT[64 * QS];
    __shared__ float KsT[64 * KS];
    __shared__ float Vs[32 * 64];
    __shared__ float Ss[64 * SS];
    int b = blockIdx.z, h = blockIdx.y;
    int n0 = blockIdx.x * 64;
    int tid = threadIdx.x;
    int tx = tid & 15, ty = tid >> 4;
    float gamma = 1.f - exp2f(-5.f - (float)h);
    float l2g = log2f(gamma);

    {
        int row = tid >> 2, cq = tid & 3;
        const float* src = g_q + ((size_t)(b * SEQ + n0 + row)) * DIM + h * HDIM;
#pragma unroll
        for (int rep = 0; rep < 4; rep++) {
            int c = (cq + rep * 4) * 4;
            float4 v = *(const float4*)(src + c);
            QsT[(c + 0) * QS + row] = v.x;
            QsT[(c + 1) * QS + row] = v.y;
            QsT[(c + 2) * QS + row] = v.z;
            QsT[(c + 3) * QS + row] = v.w;
        }
    }

    float acc[4][4] = {};
    for (int m0 = 0; m0 <= n0 + 32; m0 += 32) {
        __syncthreads();
        {
            int row = tid >> 3, cq = tid & 7;
            const float* ksrc = g_k + ((size_t)(b * SEQ + m0 + row)) * DIM + h * HDIM;
            const float* vsrc = g_v + ((size_t)(b * SEQ + m0 + row)) * DIM + h * HDIM;
#pragma unroll
            for (int rep = 0; rep < 2; rep++) {
                int c = cq * 8 + rep * 4;
                float4 kv = *(const float4*)(ksrc + c);
                KsT[(c + 0) * KS + row] = kv.x;
                KsT[(c + 1) * KS + row] = kv.y;
                KsT[(c + 2) * KS + row] = kv.z;
                KsT[(c + 3) * KS + row] = kv.w;
                *(float4*)&Vs[row * 64 + c] = *(const float4*)(vsrc + c);
            }
        }
        __syncthreads();
        float s[4][2] = {};
#pragma unroll 8
        for (int d = 0; d < 64; d++) {
            float a[4], bb[2];
            *(float4*)a  = *(const float4*)&QsT[d * QS + ty * 4];
            *(float2*)bb = *(const float2*)&KsT[d * KS + tx * 2];
#pragma unroll
            for (int i = 0; i < 4; i++)
#pragma unroll
                for (int j = 0; j < 2; j++) s[i][j] += a[i] * bb[j];
        }
#pragma unroll
        for (int i = 0; i < 4; i++)
#pragma unroll
            for (int j = 0; j < 2; j++) {
                int diff = (n0 + ty * 4 + i) - (m0 + tx * 2 + j);
                float val = (diff < 0) ? 0.f
                          : s[i][j] * 0.125f * exp2f((float)diff * l2g);
                Ss[(ty * 4 + i) * SS + tx * 2 + j] = val;
            }
        __syncthreads();
#pragma unroll 8
        for (int m = 0; m < 32; m++) {
            float a[4], bb[4];
#pragma unroll
            for (int i = 0; i < 4; i++) a[i] = Ss[(ty * 4 + i) * SS + m];
            *(float4*)bb = *(const float4*)&Vs[m * 64 + tx * 4];
#pragma unroll
            for (int i = 0; i < 4; i++)
#pragma unroll
                for (int j = 0; j < 4; j++) acc[i][j] += a[i] * bb[j];
        }
    }

#pragma unroll
    for (int i = 0; i < 4; i++) {
        float s1 = acc[i][0] + acc[i][1] + acc[i][2] + acc[i][3];
        float s2 = acc[i][0] * acc[i][0] + acc[i][1] * acc[i][1] +
                   acc[i][2] * acc[i][2] + acc[i][3] * acc[i][3];
#pragma unroll
        for (int o = 8; o; o >>= 1) {
            s1 += __shfl_xor_sync(0xffffffffu, s1, o);
            s2 += __shfl_xor_sync(0xffffffffu, s2, o);
        }
        float mean = s1 * (1.f / 64.f);
        float var = s2 * (1.f / 64.f) - mean * mean;
        float r = rsqrtf(var + EPSF);
        int n = n0 + ty * 4 + i;
        float4 o4;
        o4.x = (acc[i][0] - mean) * r;
        o4.y = (acc[i][1] - mean) * r;
        o4.z = (acc[i][2] - mean) * r;
        o4.w = (acc[i][3] - mean) * r;
        *(float4*)&g_y[((size_t)(b * SEQ + n)) * DIM + h * HDIM + tx * 4] = o4;
    }
}

// ---------------- gate: z = swish(xg) * y -> a-pair bf16 ----------------
__global__ void gate_kernel() {
    int i = blockIdx.x * blockDim.x + threadIdx.x;
    float4 g = ((const float4*)g_g)[i];
    float4 y = ((const float4*)g_y)[i];
    float4 o;
    o.x = g.x * y.x / (1.f + expf(-g.x));
    o.y = g.y * y.y / (1.f + expf(-g.y));
    o.z = g.z * y.z / (1.f + expf(-g.z));
    o.w = g.w * y.w / (1.f + expf(-g.w));
    ((float4*)g_g)[i] = o;
    size_t i0 = (size_t)i * 4;
    split_store(g_ah, g_al, i0 + 0, o.x);
    split_store(g_ah, g_al, i0 + 1, o.y);
    split_store(g_ah, g_al, i0 + 2, o.z);
    split_store(g_ah, g_al, i0 + 3, o.w);
}

// ---------------- final: out[b] = sigmoid(x5[b].flatten() . fc_W + fc_b) ----------------
__global__ void final_kernel(int in_sel,
                             const float* __restrict__ w,
                             const float* __restrict__ bias,
                             float* __restrict__ out) {
    int b = blockIdx.x;
    const float* x = buf(in_sel);
    const float4* xr = (const float4*)(x + (size_t)b * SEQ * DIM);
    const float4* wr = (const float4*)w;
    float sum = 0.f;
    const int n4 = SEQ * DIM / 4;
    for (int i = threadIdx.x; i < n4; i += blockDim.x) {
        float4 a = xr[i], c = wr[i];
        sum += a.x * c.x + a.y * c.y + a.z * c.z + a.w * c.w;
    }
    __shared__ float red[32];
#pragma unroll
    for (int o = 16; o; o >>= 1) sum += __shfl_xor_sync(0xffffffffu, sum, o);
    if ((threadIdx.x & 31) == 0) red[threadIdx.x >> 5] = sum;
    __syncthreads();
    if (threadIdx.x < 32) {
        float v = (threadIdx.x < (int)(blockDim.x >> 5)) ? red[threadIdx.x] : 0.f;
#pragma unroll
        for (int o = 16; o; o >>= 1) v += __shfl_xor_sync(0xffffffffu, v, o);
        if (threadIdx.x == 0) out[b] = 1.f / (1.f + expf(-(v + bias[0])));
    }
}

// ---------------- launch: kernel launches ONLY ----------------
extern "C" void kernel_launch(void* const* d_in, const int* in_sizes, int n_in,
                              void* d_out, int out_size) {
    (void)in_sizes; (void)n_in; (void)out_size;
    const int*   ids    = (const int*)d_in[0];
    const float* tables = (const float*)d_in[1];
    const float* pos    = (const float*)d_in[2];
    const float* lng    = (const float*)d_in[3];
    const float* lnb    = (const float*)d_in[4];
    const float* Wq     = (const float*)d_in[5];
    const float* Wk     = (const float*)d_in[6];
    const float* Wv     = (const float*)d_in[7];
    const float* Wg     = (const float*)d_in[8];
    const float* Wo     = (const float*)d_in[9];
    const float* W1     = (const float*)d_in[10];
    const float* b1     = (const float*)d_in[11];
    const float* W2     = (const float*)d_in[12];
    const float* b2     = (const float*)d_in[13];
    const float* fcW    = (const float*)d_in[14];
    const float* fcb    = (const float*)d_in[15];
    float* out = (float*)d_out;

    dim3 gw(16, 16, 7);
    dim3 bw(32, 8);
    dim3 g1(4, M_ROWS / 128);    // single-weight GEMM: 256 CTAs
    dim3 g4(16, M_ROWS / 128);   // fused QKVG GEMM: 1024 CTAs

    // Only the last vocab pass (i = NVOCAB-1 = 2) survives in the reference.
    convert_weights_kernel<<<gw, bw>>>(Wq, Wk, Wv, Wg, Wo, W1, W2);
    embed_ln_kernel<<<M_ROWS / 8, 256>>>(ids, tables, pos, lng, lnb);   // -> g_x + a-pair
    // q(1), k(2), v(3), gate(4): weights 0..3, A = a-pair
    mma_gemm_kernel<<<g4, 256>>>(0, 0, 0x04030201, nullptr, 0, 0);
    retention_kernel<<<dim3(SEQ / 64, HEADS, BATCH), 256>>>();          // -> g_y(5)
    gate_kernel<<<MTOT / 4 / 256, 256>>>();                             // z -> a-pair
    mma_gemm_kernel<<<g1, 256>>>(0, 4, 6, nullptr, 0, 4);               // x2 = z@Wo + x(0) -> t(6)
    ln_kernel<<<M_ROWS / 8, 256>>>(6, 0, lng, lnb);                     // x3 -> g_x + a-pair
    mma_gemm_kernel<<<g1, 256>>>(0, 5, 1, b1, 0, 1 | 2 | 8);            // h = relu(x3@W1+b1) -> b-pair
    mma_gemm_kernel<<<g1, 256>>>(1, 6, 3, b2, 6, 1 | 4);                // x4 = h@W2+b2+x2 -> v(3)
    ln_kernel<<<M_ROWS / 8, 256>>>(3, 2, lng, lnb);                     // x5 -> k(2)
    final_kernel<<<BATCH, 1024>>>(2, fcW, fcb, out);
}

// round 13
// speedup vs baseline: 1.8173x; 1.2979x over previous
#include <cuda_runtime.h>
#include <cuda_bf16.h>
#include <math.h>
#include <stdint.h>

#define BATCH 8
#define SEQ 1024
#define DIM 512
#define HEADS 8
#define HDIM 64
#define VOCAB 1024
#define M_ROWS (BATCH*SEQ)          /* 8192 */
#define MTOT (M_ROWS*DIM)           /* 4,194,304 floats */
#define EPSF 1e-5f

// ---------------- scratch (device globals; no allocation allowed) ----------------
__device__ float g_x[MTOT];   // 0: x (post embed-LN)
__device__ float g_q[MTOT];   // 1: q proj / FFN hidden
__device__ float g_k[MTOT];   // 2: k proj / final LN output
__device__ float g_v[MTOT];   // 3: v proj / x4
__device__ float g_g[MTOT];   // 4: gate proj / z
__device__ float g_y[MTOT];   // 5: retention output (group-normed)
__device__ float g_t[MTOT];   // 6: x2 = z@Wo + x (residual carrier)

// bf16 split activation buffers
__device__ __nv_bfloat16 g_ah[MTOT], g_al[MTOT];   // generic a-pair (GEMM A)
__device__ __nv_bfloat16 g_bh[MTOT], g_bl[MTOT];   // b-pair (FFN hidden)
__device__ __nv_bfloat16 g_qh[MTOT], g_ql[MTOT];   // q split
__device__ __nv_bfloat16 g_kh[MTOT], g_kl[MTOT];   // k split
__device__ __nv_bfloat16 g_vh[MTOT], g_vl[MTOT];   // v split

// bf16 split transposed weights: 7 matrices [n][k]: Wq,Wk,Wv,Wg,Wo,W1,W2
__device__ __nv_bfloat16 g_wh[7 * DIM * DIM];
__device__ __nv_bfloat16 g_wl[7 * DIM * DIM];

__device__ __forceinline__ float* buf(int s) {
    switch (s) {
        case 0: return g_x;
        case 1: return g_q;
        case 2: return g_k;
        case 3: return g_v;
        case 4: return g_g;
        case 5: return g_y;
        default: return g_t;
    }
}

__device__ __forceinline__ void split_dst(int id, __nv_bfloat16** hp, __nv_bfloat16** lp) {
    switch (id) {
        case 1: *hp = g_qh; *lp = g_ql; break;
        case 2: *hp = g_kh; *lp = g_kl; break;
        case 3: *hp = g_vh; *lp = g_vl; break;
        case 4: *hp = g_bh; *lp = g_bl; break;
        default: *hp = 0;   *lp = 0;    break;
    }
}

__device__ __forceinline__ void split_store(__nv_bfloat16* hp, __nv_bfloat16* lp,
                                            size_t idx, float v) {
    __nv_bfloat16 h = __float2bfloat16(v);
    hp[idx] = h;
    lp[idx] = __float2bfloat16(v - __bfloat162float(h));
}

__device__ __forceinline__ uint32_t smem_u32(const void* p) {
    uint32_t a;
    asm("{ .reg .u64 t; cvta.to.shared.u64 t, %1; cvt.u32.u64 %0, t; }"
        : "=r"(a) : "l"(p));
    return a;
}

// ---------------- mma.sync helpers (baseline ISA) ----------------
__device__ __forceinline__ void ldsm4(uint32_t* r, uint32_t addr) {
    asm volatile("ldmatrix.sync.aligned.m8n8.x4.shared.b16 {%0,%1,%2,%3}, [%4];"
                 : "=r"(r[0]), "=r"(r[1]), "=r"(r[2]), "=r"(r[3]) : "r"(addr));
}
__device__ __forceinline__ void ldsm4t(uint32_t* r, uint32_t addr) {
    asm volatile("ldmatrix.sync.aligned.m8n8.x4.trans.shared.b16 {%0,%1,%2,%3}, [%4];"
                 : "=r"(r[0]), "=r"(r[1]), "=r"(r[2]), "=r"(r[3]) : "r"(addr));
}
__device__ __forceinline__ void mma_bf16(float* d, const uint32_t* a, const uint32_t* b) {
    asm volatile("mma.sync.aligned.m16n8k16.row.col.f32.bf16.bf16.f32 "
                 "{%0,%1,%2,%3}, {%4,%5,%6,%7}, {%8,%9}, {%0,%1,%2,%3};"
                 : "+f"(d[0]), "+f"(d[1]), "+f"(d[2]), "+f"(d[3])
                 : "r"(a[0]), "r"(a[1]), "r"(a[2]), "r"(a[3]), "r"(b[0]), "r"(b[1]));
}
// pack two fp32 -> bf16x2 hi, residual bf16x2 lo
__device__ __forceinline__ uint32_t pack_split(float v0, float v1, uint32_t& lo) {
    __nv_bfloat162 h = __floats2bfloat162_rn(v0, v1);
    __nv_bfloat162 l = __floats2bfloat162_rn(v0 - __bfloat162float(h.x),
                                             v1 - __bfloat162float(h.y));
    lo = *reinterpret_cast<uint32_t*>(&l);
    return *reinterpret_cast<uint32_t*>(&h);
}

// ---------------- weight convert: transpose + bf16 hi/lo split ----------------
__global__ void convert_weights_kernel(const float* __restrict__ Wq, const float* __restrict__ Wk,
                                       const float* __restrict__ Wv, const float* __restrict__ Wg,
                                       const float* __restrict__ Wo, const float* __restrict__ W1,
                                       const float* __restrict__ W2) {
    __shared__ float tile[32][33];
    int widx = blockIdx.z;
    const float* W = (widx == 0) ? Wq : (widx == 1) ? Wk : (widx == 2) ? Wv
                   : (widx == 3) ? Wg : (widx == 4) ? Wo : (widx == 5) ? W1 : W2;
    int k0 = blockIdx.x * 32, n0 = blockIdx.y * 32;
    int tx = threadIdx.x, ty = threadIdx.y;
#pragma unroll
    for (int r = 0; r < 32; r += 8)
        tile[ty + r][tx] = W[(size_t)(k0 + ty + r) * DIM + n0 + tx];
    __syncthreads();
    size_t base = (size_t)widx * DIM * DIM;
#pragma unroll
    for (int r = 0; r < 32; r += 8) {
        float v = tile[tx][ty + r];
        size_t o = base + (size_t)(n0 + ty + r) * DIM + k0 + tx;
        __nv_bfloat16 h = __float2bfloat16(v);
        g_wh[o] = h;
        g_wl[o] = __float2bfloat16(v - __bfloat162float(h));
    }
}

// ---------------- embed + layernorm (warp per row) + bf16 split out ----------------
__global__ void embed_ln_kernel(const int* __restrict__ ids,
                                const float* __restrict__ tables,
                                const float* __restrict__ pos,
                                const float* __restrict__ gam,
                                const float* __restrict__ bet) {
    int warp = (blockIdx.x * blockDim.x + threadIdx.x) >> 5;
    if (warp >= M_ROWS) return;
    int lane = threadIdx.x & 31;
    int s = warp & (SEQ - 1);
    int id = ids[2 * BATCH * SEQ + warp];
    const float4* t4 = (const float4*)(tables + (size_t)(2 * VOCAB + id) * DIM);
    const float4* p4 = (const float4*)(pos + (size_t)(2 * SEQ + s) * DIM);
    float4 v[4];
    float s1 = 0.f, s2 = 0.f;
#pragma unroll
    for (int k = 0; k < 4; k++) {
        int c4 = lane + k * 32;
        float4 a = t4[c4], b = p4[c4];
        v[k] = make_float4(a.x + b.x, a.y + b.y, a.z + b.z, a.w + b.w);
        s1 += v[k].x + v[k].y + v[k].z + v[k].w;
        s2 += v[k].x * v[k].x + v[k].y * v[k].y + v[k].z * v[k].z + v[k].w * v[k].w;
    }
#pragma unroll
    for (int o = 16; o; o >>= 1) {
        s1 += __shfl_xor_sync(0xffffffffu, s1, o);
        s2 += __shfl_xor_sync(0xffffffffu, s2, o);
    }
    float mean = s1 * (1.f / DIM);
    float var = s2 * (1.f / DIM) - mean * mean;
    float r = rsqrtf(var + EPSF);
    size_t rowoff = (size_t)warp * DIM;
    float4* out4 = (float4*)(g_x + rowoff);
#pragma unroll
    for (int k = 0; k < 4; k++) {
        int c4 = lane + k * 32;
        float4 gm = ((const float4*)gam)[c4];
        float4 bt = ((const float4*)bet)[c4];
        float4 o;
        o.x = (v[k].x - mean) * r * gm.x + bt.x;
        o.y = (v[k].y - mean) * r * gm.y + bt.y;
        o.z = (v[k].z - mean) * r * gm.z + bt.z;
        o.w = (v[k].w - mean) * r * gm.w + bt.w;
        out4[c4] = o;
        size_t i0 = rowoff + c4 * 4;
        split_store(g_ah, g_al, i0 + 0, o.x);
        split_store(g_ah, g_al, i0 + 1, o.y);
        split_store(g_ah, g_al, i0 + 2, o.z);
        split_store(g_ah, g_al, i0 + 3, o.w);
    }
}

// ---------------- plain layernorm (warp per row) + bf16 split out ----------------
__global__ void ln_kernel(int in_sel, int out_sel,
                          const float* __restrict__ gam,
                          const float* __restrict__ bet) {
    int warp = (blockIdx.x * blockDim.x + threadIdx.x) >> 5;
    if (warp >= M_ROWS) return;
    int lane = threadIdx.x & 31;
    const float* in = buf(in_sel);
    float* out = buf(out_sel);
    const float4* src = (const float4*)(in + (size_t)warp * DIM);
    float4 v[4];
    float s1 = 0.f, s2 = 0.f;
#pragma unroll
    for (int k = 0; k < 4; k++) {
        int c4 = lane + k * 32;
        v[k] = src[c4];
        s1 += v[k].x + v[k].y + v[k].z + v[k].w;
        s2 += v[k].x * v[k].x + v[k].y * v[k].y + v[k].z * v[k].z + v[k].w * v[k].w;
    }
#pragma unroll
    for (int o = 16; o; o >>= 1) {
        s1 += __shfl_xor_sync(0xffffffffu, s1, o);
        s2 += __shfl_xor_sync(0xffffffffu, s2, o);
    }
    float mean = s1 * (1.f / DIM);
    float var = s2 * (1.f / DIM) - mean * mean;
    float r = rsqrtf(var + EPSF);
    size_t rowoff = (size_t)warp * DIM;
    float4* out4 = (float4*)(out + rowoff);
#pragma unroll
    for (int k = 0; k < 4; k++) {
        int c4 = lane + k * 32;
        float4 gm = ((const float4*)gam)[c4];
        float4 bt = ((const float4*)bet)[c4];
        float4 o;
        o.x = (v[k].x - mean) * r * gm.x + bt.x;
        o.y = (v[k].y - mean) * r * gm.y + bt.y;
        o.z = (v[k].z - mean) * r * gm.z + bt.z;
        o.w = (v[k].w - mean) * r * gm.w + bt.w;
        out4[c4] = o;
        size_t i0 = rowoff + c4 * 4;
        split_store(g_ah, g_al, i0 + 0, o.x);
        split_store(g_ah, g_al, i0 + 1, o.y);
        split_store(g_ah, g_al, i0 + 2, o.z);
        split_store(g_ah, g_al, i0 + 3, o.w);
    }
}

// ---------------- HMMA split-bf16 GEMM (proven in R12) ----------------
// spack: 4-bit per 'which' split-pair destination id (0 none / 1 q / 2 k / 3 v / 4 b)
#define SROW 40
__global__ __launch_bounds__(256, 2) void mma_gemm_kernel(int a_sel, int wbase, int cpack,
                                                          const float* __restrict__ bias,
                                                          int res_sel, int flags, int spack) {
    __shared__ __nv_bfloat16 sA[128 * SROW];
    __shared__ __nv_bfloat16 sBh[128 * SROW];
    __shared__ __nv_bfloat16 sBl[128 * SROW];
    const int tid = threadIdx.x;
    const int lane = tid & 31, wid = tid >> 5;
    const int wm = wid & 3, wn = wid >> 2;
    const int which = blockIdx.x >> 2;
    const int bn = (blockIdx.x & 3) * 128;
    const int bm = blockIdx.y * 128;
    const size_t woff = (size_t)(wbase + which) * DIM * DIM;
    const __nv_bfloat16* Ah = a_sel ? g_bh : g_ah;
    const __nv_bfloat16* Al = a_sel ? g_bl : g_al;

    const int lrow = tid >> 1, lhalf = tid & 1;
    const int sOff = lrow * SROW + lhalf * 16;
    const size_t aRow = (size_t)(bm + lrow) * DIM + lhalf * 16;
    const size_t bRow = woff + (size_t)(bn + lrow) * DIM + lhalf * 16;

    const int mtx = lane >> 3, lr = lane & 7;
    const uint32_t aBase = smem_u32(sA), bhBase = smem_u32(sBh), blBase = smem_u32(sBl);
    const uint32_t aOff = (uint32_t)(((mtx & 1) * 8 + lr) * (SROW * 2) + (mtx >> 1) * 16);
    const uint32_t bOff = (uint32_t)(((mtx >> 1) * 8 + lr) * (SROW * 2) + (mtx & 1) * 16);

    float acc[2][8][4];
#pragma unroll
    for (int i = 0; i < 2; i++)
#pragma unroll
        for (int j = 0; j < 8; j++)
#pragma unroll
            for (int c = 0; c < 4; c++) acc[i][j][c] = 0.f;

    uint4 pa0, pa1, pbh0, pbh1, pbl0, pbl1;
#define FETCH(step) do {                                                    \
        int ph_ = (step) >> 4, k0_ = ((step) & 15) * 32;                    \
        const __nv_bfloat16* As_ = ph_ ? Al : Ah;                           \
        pa0  = *(const uint4*)(As_ + aRow + k0_);                           \
        pa1  = *(const uint4*)(As_ + aRow + k0_ + 8);                       \
        pbh0 = *(const uint4*)(g_wh + bRow + k0_);                          \
        pbh1 = *(const uint4*)(g_wh + bRow + k0_ + 8);                      \
        if (ph_ == 0) {                                                     \
            pbl0 = *(const uint4*)(g_wl + bRow + k0_);                      \
            pbl1 = *(const uint4*)(g_wl + bRow + k0_ + 8);                  \
        }                                                                   \
    } while (0)
#define STORE(step) do {                                                    \
        int ph_ = (step) >> 4;                                              \
        *(uint4*)(sA + sOff) = pa0;  *(uint4*)(sA + sOff + 8) = pa1;        \
        *(uint4*)(sBh + sOff) = pbh0; *(uint4*)(sBh + sOff + 8) = pbh1;     \
        if (ph_ == 0) { *(uint4*)(sBl + sOff) = pbl0;                       \
                        *(uint4*)(sBl + sOff + 8) = pbl1; }                 \
    } while (0)

    FETCH(0);
    STORE(0);
    __syncthreads();
#pragma unroll 1
    for (int step = 0; step < 32; step++) {
        int ph = step >> 4;
        if (step < 31) FETCH(step + 1);
#pragma unroll
        for (int ks = 0; ks < 2; ks++) {
            uint32_t a[2][4];
            ldsm4(a[0], aBase + (uint32_t)((wm * 32) * (SROW * 2)) + ks * 32 + aOff);
            ldsm4(a[1], aBase + (uint32_t)((wm * 32 + 16) * (SROW * 2)) + ks * 32 + aOff);
#pragma unroll
            for (int nfp = 0; nfp < 4; nfp++) {
                uint32_t b[4];
                uint32_t bo = (uint32_t)((wn * 64 + nfp * 16) * (SROW * 2)) + ks * 32 + bOff;
                ldsm4(b, bhBase + bo);
                mma_bf16(acc[0][2 * nfp],     a[0], b + 0);
                mma_bf16(acc[0][2 * nfp + 1], a[0], b + 2);
                mma_bf16(acc[1][2 * nfp],     a[1], b + 0);
                mma_bf16(acc[1][2 * nfp + 1], a[1], b + 2);
                if (ph == 0) {
                    ldsm4(b, blBase + bo);
                    mma_bf16(acc[0][2 * nfp],     a[0], b + 0);
                    mma_bf16(acc[0][2 * nfp + 1], a[0], b + 2);
                    mma_bf16(acc[1][2 * nfp],     a[1], b + 0);
                    mma_bf16(acc[1][2 * nfp + 1], a[1], b + 2);
                }
            }
        }
        if (step < 31) {
            __syncthreads();
            STORE(step + 1);
            __syncthreads();
        }
    }
#undef FETCH
#undef STORE

    bool hb = flags & 1, hr = flags & 2, hres = flags & 4;
    float* C = buf((cpack >> (8 * which)) & 0xf);
    const float* res = hres ? buf(res_sel) : (const float*)0;
    __nv_bfloat16 *sh, *sl;
    split_dst((spack >> (4 * which)) & 0xf, &sh, &sl);
    int group = lane >> 2, tig = lane & 3;
#pragma unroll
    for (int mf = 0; mf < 2; mf++) {
#pragma unroll
        for (int nf = 0; nf < 8; nf++) {
            int row0 = bm + wm * 32 + mf * 16 + group;
            int col = bn + wn * 64 + nf * 8 + tig * 2;
            float b0 = hb ? bias[col] : 0.f;
            float b1 = hb ? bias[col + 1] : 0.f;
#pragma unroll
            for (int half = 0; half < 2; half++) {
                int row = row0 + half * 8;
                float v0 = acc[mf][nf][half * 2 + 0] + b0;
                float v1 = acc[mf][nf][half * 2 + 1] + b1;
                if (hr) { v0 = fmaxf(v0, 0.f); v1 = fmaxf(v1, 0.f); }
                size_t co = (size_t)row * DIM + col;
                if (hres) {
                    float2 rr = *(const float2*)(res + co);
                    v0 += rr.x; v1 += rr.y;
                }
                *(float2*)(C + co) = make_float2(v0, v1);
                if (sh) {
                    split_store(sh, sl, co, v0);
                    split_store(sh, sl, co + 1, v1);
                }
            }
        }
    }
}

// ---------------- HMMA retention: causal (QK^T ∘ decay)·V + group norm ----------------
// Block: 128 Q rows of one (b,h), 8 warps x 16 rows. Chunks of 64 keys.
// Split-bf16 3-term products in both stages; S stays in registers (C->A repack).
#define RST 72   /* smem row stride (bf16): 144B, 16B-aligned, ldmatrix conflict-free */
__global__ __launch_bounds__(256) void retention_kernel() {
    __shared__ __align__(16) __nv_bfloat16 sKh[64 * RST];
    __shared__ __align__(16) __nv_bfloat16 sKl[64 * RST];
    __shared__ __align__(16) __nv_bfloat16 sVh[64 * RST];
    __shared__ __align__(16) __nv_bfloat16 sVl[64 * RST];
    const int b = blockIdx.z, h = blockIdx.y;
    const int n0 = blockIdx.x * 128;
    const int tid = threadIdx.x, lane = tid & 31, wid = tid >> 5;
    const int g = lane >> 2, t = lane & 3;
    const float l2g = log2f(1.f - exp2f(-5.f - (float)h));

    // preload q A-fragments (16 rows per warp, hd=64 -> 4 k-steps) from global
    uint32_t aqh[4][4], aql[4][4];
    {
        const size_t qb = ((size_t)(b * SEQ + n0 + wid * 16 + g)) * DIM + h * HDIM + 2 * t;
#pragma unroll
        for (int ks = 0; ks < 4; ks++) {
            size_t p = qb + ks * 16;
            aqh[ks][0] = *(const uint32_t*)&g_qh[p];
            aqh[ks][1] = *(const uint32_t*)&g_qh[p + 8 * DIM];
            aqh[ks][2] = *(const uint32_t*)&g_qh[p + 8];
            aqh[ks][3] = *(const uint32_t*)&g_qh[p + 8 * DIM + 8];
            aql[ks][0] = *(const uint32_t*)&g_ql[p];
            aql[ks][1] = *(const uint32_t*)&g_ql[p + 8 * DIM];
            aql[ks][2] = *(const uint32_t*)&g_ql[p + 8];
            aql[ks][3] = *(const uint32_t*)&g_ql[p + 8 * DIM + 8];
        }
    }

    // decay factors: 0.125 * gamma^(n-m) = rowf(gamma^drow) * colf(gamma^-mloc)
    const float gstep = exp2f(-64.f * l2g);   // gamma^-64 (per-chunk rowf update)
    const float g8    = exp2f(8.f * l2g);     // gamma^8
    const float g8i   = exp2f(-8.f * l2g);    // gamma^-8
    const float ginv  = exp2f(-l2g);          // gamma^-1
    const float clane = exp2f(-(float)(2 * t) * l2g);
    float rowf = 0.125f * exp2f((float)(n0 + wid * 16 + g) * l2g);

    // smem fill addressing: thread -> (row = tid/4, 32B segment = tid%4)
    const int frow = tid >> 2, fq = tid & 3;
    const int fdst = frow * RST + fq * 16;
    // ldmatrix lane offsets
    const int mtx = lane >> 3, lr = lane & 7;
    const uint32_t khB = smem_u32(sKh), klB = smem_u32(sKl);
    const uint32_t vhB = smem_u32(sVh), vlB = smem_u32(sVl);
    const uint32_t kOff = (uint32_t)((((mtx >> 1) * 8 + lr) * RST + (mtx & 1) * 8) * 2);
    const uint32_t vOff = (uint32_t)((((lane & 7) + ((lane >> 3) & 1) * 8) * RST + (lane >> 4) * 8) * 2);

    float yacc[8][4];
#pragma unroll
    for (int f = 0; f < 8; f++)
#pragma unroll
        for (int c = 0; c < 4; c++) yacc[f][c] = 0.f;

    const int nchunks = n0 / 64 + 2;
    for (int ch = 0; ch < nchunks; ch++) {
        const int m0 = ch * 64;
        __syncthreads();
        {   // fill K/V split tiles (64 rows x 64 bf16 each)
            size_t src = ((size_t)(b * SEQ + m0 + frow)) * DIM + h * HDIM + fq * 16;
            *(uint4*)&sKh[fdst]     = *(const uint4*)&g_kh[src];
            *(uint4*)&sKh[fdst + 8] = *(const uint4*)&g_kh[src + 8];
            *(uint4*)&sKl[fdst]     = *(const uint4*)&g_kl[src];
            *(uint4*)&sKl[fdst + 8] = *(const uint4*)&g_kl[src + 8];
            *(uint4*)&sVh[fdst]     = *(const uint4*)&g_vh[src];
            *(uint4*)&sVh[fdst + 8] = *(const uint4*)&g_vh[src + 8];
            *(uint4*)&sVl[fdst]     = *(const uint4*)&g_vl[src];
            *(uint4*)&sVl[fdst + 8] = *(const uint4*)&g_vl[src + 8];
        }
        __syncthreads();
        if (n0 + wid * 16 + 15 >= m0) {   // warp has at least one unmasked row
            // ---- stage 1: S = q.k (3-term split), fp32 in regs ----
            float sacc[8][4];
#pragma unroll
            for (int f = 0; f < 8; f++)
#pragma unroll
                for (int c = 0; c < 4; c++) sacc[f][c] = 0.f;
#pragma unroll
            for (int ks = 0; ks < 4; ks++) {
#pragma unroll
                for (int ng = 0; ng < 4; ng++) {
                    uint32_t kb[4], kb2[4];
                    uint32_t off = (uint32_t)((ng * 16 * RST + ks * 16) * 2);
                    ldsm4(kb, khB + kOff + off);
                    ldsm4(kb2, klB + kOff + off);
                    mma_bf16(sacc[2 * ng],     aqh[ks], kb + 0);
                    mma_bf16(sacc[2 * ng + 1], aqh[ks], kb + 2);
                    mma_bf16(sacc[2 * ng],     aqh[ks], kb2 + 0);
                    mma_bf16(sacc[2 * ng + 1], aqh[ks], kb2 + 2);
                    mma_bf16(sacc[2 * ng],     aql[ks], kb + 0);
                    mma_bf16(sacc[2 * ng + 1], aql[ks], kb + 2);
                }
            }
            // ---- decay + causal mask (in registers) ----
            {
                int drow = n0 + wid * 16 + g - m0;
                float rf0 = rowf, rf8 = rowf * g8;
                float ce = clane;
#pragma unroll
                for (int f = 0; f < 8; f++) {
                    float co = ce * ginv;
                    int me = f * 8 + 2 * t;
                    sacc[f][0] = (drow - me     >= 0) ? sacc[f][0] * rf0 * ce : 0.f;
                    sacc[f][1] = (drow - me - 1 >= 0) ? sacc[f][1] * rf0 * co : 0.f;
                    sacc[f][2] = (drow + 8 - me     >= 0) ? sacc[f][2] * rf8 * ce : 0.f;
                    sacc[f][3] = (drow + 8 - me - 1 >= 0) ? sacc[f][3] * rf8 * co : 0.f;
                    ce *= g8i;
                }
            }
            // ---- stage 2: y += S.V (C->A repack, 3-term split) ----
#pragma unroll
            for (int ks2 = 0; ks2 < 4; ks2++) {
                int f0 = 2 * ks2, f1 = f0 + 1;
                uint32_t ash[4], asl[4];
                ash[0] = pack_split(sacc[f0][0], sacc[f0][1], asl[0]);
                ash[1] = pack_split(sacc[f0][2], sacc[f0][3], asl[1]);
                ash[2] = pack_split(sacc[f1][0], sacc[f1][1], asl[2]);
                ash[3] = pack_split(sacc[f1][2], sacc[f1][3], asl[3]);
#pragma unroll
                for (int cg = 0; cg < 4; cg++) {
                    uint32_t vb[4], vb2[4];
                    uint32_t off = (uint32_t)((ks2 * 16 * RST + cg * 16) * 2);
                    ldsm4t(vb, vhB + vOff + off);
                    ldsm4t(vb2, vlB + vOff + off);
                    mma_bf16(yacc[2 * cg],     ash, vb + 0);
                    mma_bf16(yacc[2 * cg + 1], ash, vb + 2);
                    mma_bf16(yacc[2 * cg],     ash, vb2 + 0);
                    mma_bf16(yacc[2 * cg + 1], ash, vb2 + 2);
                    mma_bf16(yacc[2 * cg],     asl, vb + 0);
                    mma_bf16(yacc[2 * cg + 1], asl, vb + 2);
                }
            }
        }
        rowf *= gstep;
    }

    // ---- per-row group norm over hd=64 + store ----
#pragma unroll
    for (int half = 0; half < 2; half++) {
        float s1 = 0.f, s2 = 0.f;
#pragma unroll
        for (int f = 0; f < 8; f++) {
            float v0 = yacc[f][2 * half], v1 = yacc[f][2 * half + 1];
            s1 += v0 + v1;
            s2 += v0 * v0 + v1 * v1;
        }
        s1 += __shfl_xor_sync(0xffffffffu, s1, 1);
        s2 += __shfl_xor_sync(0xffffffffu, s2, 1);
        s1 += __shfl_xor_sync(0xffffffffu, s1, 2);
        s2 += __shfl_xor_sync(0xffffffffu, s2, 2);
        float mean = s1 * (1.f / 64.f);
        float var = s2 * (1.f / 64.f) - mean * mean;
        float r = rsqrtf(var + EPSF);
        size_t row = (size_t)(b * SEQ + n0 + wid * 16 + g + half * 8);
#pragma unroll
        for (int f = 0; f < 8; f++) {
            float2 o = make_float2((yacc[f][2 * half] - mean) * r,
                                   (yacc[f][2 * half + 1] - mean) * r);
            *(float2*)&g_y[row * DIM + h * HDIM + f * 8 + 2 * t] = o;
        }
    }
}

// ---------------- gate: z = swish(xg) * y -> a-pair bf16 ----------------
__global__ void gate_kernel() {
    int i = blockIdx.x * blockDim.x + threadIdx.x;
    float4 g = ((const float4*)g_g)[i];
    float4 y = ((const float4*)g_y)[i];
    float4 o;
    o.x = g.x * y.x / (1.f + expf(-g.x));
    o.y = g.y * y.y / (1.f + expf(-g.y));
    o.z = g.z * y.z / (1.f + expf(-g.z));
    o.w = g.w * y.w / (1.f + expf(-g.w));
    ((float4*)g_g)[i] = o;
    size_t i0 = (size_t)i * 4;
    split_store(g_ah, g_al, i0 + 0, o.x);
    split_store(g_ah, g_al, i0 + 1, o.y);
    split_store(g_ah, g_al, i0 + 2, o.z);
    split_store(g_ah, g_al, i0 + 3, o.w);
}

// ---------------- final: out[b] = sigmoid(x5[b].flatten() . fc_W + fc_b) ----------------
__global__ void final_kernel(int in_sel,
                             const float* __restrict__ w,
                             const float* __restrict__ bias,
                             float* __restrict__ out) {
    int b = blockIdx.x;
    const float* x = buf(in_sel);
    const float4* xr = (const float4*)(x + (size_t)b * SEQ * DIM);
    const float4* wr = (const float4*)w;
    float sum = 0.f;
    const int n4 = SEQ * DIM / 4;
    for (int i = threadIdx.x; i < n4; i += blockDim.x) {
        float4 a = xr[i], c = wr[i];
        sum += a.x * c.x + a.y * c.y + a.z * c.z + a.w * c.w;
    }
    __shared__ float red[32];
#pragma unroll
    for (int o = 16; o; o >>= 1) sum += __shfl_xor_sync(0xffffffffu, sum, o);
    if ((threadIdx.x & 31) == 0) red[threadIdx.x >> 5] = sum;
    __syncthreads();
    if (threadIdx.x < 32) {
        float v = (threadIdx.x < (int)(blockDim.x >> 5)) ? red[threadIdx.x] : 0.f;
#pragma unroll
        for (int o = 16; o; o >>= 1) v += __shfl_xor_sync(0xffffffffu, v, o);
        if (threadIdx.x == 0) out[b] = 1.f / (1.f + expf(-(v + bias[0])));
    }
}

// ---------------- launch: kernel launches ONLY ----------------
extern "C" void kernel_launch(void* const* d_in, const int* in_sizes, int n_in,
                              void* d_out, int out_size) {
    (void)in_sizes; (void)n_in; (void)out_size;
    const int*   ids    = (const int*)d_in[0];
    const float* tables = (const float*)d_in[1];
    const float* pos    = (const float*)d_in[2];
    const float* lng    = (const float*)d_in[3];
    const float* lnb    = (const float*)d_in[4];
    const float* Wq     = (const float*)d_in[5];
    const float* Wk     = (const float*)d_in[6];
    const float* Wv     = (const float*)d_in[7];
    const float* Wg     = (const float*)d_in[8];
    const float* Wo     = (const float*)d_in[9];
    const float* W1     = (const float*)d_in[10];
    const float* b1     = (const float*)d_in[11];
    const float* W2     = (const float*)d_in[12];
    const float* b2     = (const float*)d_in[13];
    const float* fcW    = (const float*)d_in[14];
    const float* fcb    = (const float*)d_in[15];
    float* out = (float*)d_out;

    dim3 gw(16, 16, 7);
    dim3 bw(32, 8);
    dim3 g1(4, M_ROWS / 128);    // single-weight GEMM: 256 CTAs
    dim3 g4(16, M_ROWS / 128);   // fused QKVG GEMM: 1024 CTAs

    // Only the last vocab pass (i = NVOCAB-1 = 2) survives in the reference.
    convert_weights_kernel<<<gw, bw>>>(Wq, Wk, Wv, Wg, Wo, W1, W2);
    embed_ln_kernel<<<M_ROWS / 8, 256>>>(ids, tables, pos, lng, lnb);
    // q/k/v/gate GEMM; epilogue also writes q/k/v split pairs (spack 0x0321)
    mma_gemm_kernel<<<g4, 256>>>(0, 0, 0x04030201, nullptr, 0, 0, 0x0321);
    retention_kernel<<<dim3(SEQ / 128, HEADS, BATCH), 256>>>();         // -> g_y(5)
    gate_kernel<<<MTOT / 4 / 256, 256>>>();                             // z -> a-pair
    mma_gemm_kernel<<<g1, 256>>>(0, 4, 6, nullptr, 0, 4, 0);            // x2 = z@Wo + x -> t(6)
    ln_kernel<<<M_ROWS / 8, 256>>>(6, 0, lng, lnb);                     // x3 -> a-pair
    mma_gemm_kernel<<<g1, 256>>>(0, 5, 1, b1, 0, 1 | 2, 0x4);           // h = relu(x3@W1+b1) -> b-pair
    mma_gemm_kernel<<<g1, 256>>>(1, 6, 3, b2, 6, 1 | 4, 0);             // x4 = h@W2+b2+x2 -> v(3)
    ln_kernel<<<M_ROWS / 8, 256>>>(3, 2, lng, lnb);                     // x5 -> k(2)
    final_kernel<<<BATCH, 1024>>>(2, fcW, fcb, out);
}